// round 9
// baseline (speedup 1.0000x reference)
#include <cuda_runtime.h>
#include <cuda_bf16.h>

#define FULL 0xffffffffu

namespace {
constexpr int NB   = 32;
constexpr int NP   = 32;
constexpr int DD   = 12;
constexpr int PP   = 32;
constexpr int LL   = 1024;
constexpr int LOUT = 32;
constexpr int CPL  = 8;            // cols per lane
constexpr int CP2  = CPL / 2;      // packed f32x2 pairs per lane
constexpr int WBLK = 32 * CPL;     // 256 cols per warp
constexpr int NBLK = LL / WBLK;    // 4 warps per problem
constexpr float BIGV = 1e30f;
}

typedef unsigned long long u64;

// Blackwell packed fp32x2 ops (FFMA2/FADD2 in SASS — only reachable via PTX).
__device__ __forceinline__ u64 pack2(float lo, float hi) {
    u64 r; asm("mov.b64 %0, {%1, %2};" : "=l"(r) : "f"(lo), "f"(hi)); return r;
}
__device__ __forceinline__ void unpack2(u64 v, float& lo, float& hi) {
    asm("mov.b64 {%0, %1}, %2;" : "=f"(lo), "=f"(hi) : "l"(v));
}
__device__ __forceinline__ u64 ffma2(u64 a, u64 b, u64 c) {
    u64 d; asm("fma.rn.f32x2 %0, %1, %2, %3;" : "=l"(d) : "l"(a), "l"(b), "l"(c)); return d;
}
__device__ __forceinline__ u64 fadd2(u64 a, u64 b) {
    u64 d; asm("add.rn.f32x2 %0, %1, %2;" : "=l"(d) : "l"(a), "l"(b)); return d;
}

// One CTA (4 warps) per (b, n-pair): patterns n = np and np+16 against the
// same x[b]; the 96-register x chunk is shared by both problems, and each
// wavefront step performs TWO independent row updates whose dependency chains
// interleave. Warp w owns column block w (256 cols); diagonal wavefront with
// one __syncthreads per step; carries cross warps via barrier-ordered smem.
// Patterns live in a precomputed smem table (packed (-2p,-2p) + p2), read via
// broadcast LDS instead of shfl.
//
// Row recurrence (w == 1 exactly, RHO = 1.0):
//   cur[j] = c[j] + min(m[j], cur[j-1]),  m[j] = min(D[i-1,j-1], D[i-1,j])
// as composition of affine-min maps f_j(v) = min(beta_j, v + alpha_j),
// (f2 o f1) = (alpha1+alpha2, min(beta2, beta1+alpha2)): one composite
// Kogge-Stone scan per problem (5 hops, interleaved across problems).
__global__ void __launch_bounds__(128, 2)
dtw_fused_kernel(const float* __restrict__ x,
                 const float* __restrict__ patts,
                 float* __restrict__ out)
{
    const int gid  = blockIdx.x;        // 0..511
    const int b    = gid >> 4;
    const int np   = gid & 15;          // patterns np and np+16
    const int w    = threadIdx.x >> 5;  // column block 0..3
    const int lane = threadIdx.x & 31;

    __shared__ u64   pt[2][PP][DD];          // packed (-2*patt, -2*patt)
    __shared__ float p2s[2][PP];             // sum_d patt^2
    __shared__ float carry[2][NBLK - 1][PP]; // carry[p][w][i] = D_p[i][(w+1)*WBLK-1]

    // ---- build pattern table (once) ----
    if (threadIdx.x < 2 * PP) {
        const int p = threadIdx.x >> 5;      // 0..1
        const int i = threadIdx.x & 31;      // pattern row
        const float* pp = patts + (np + 16 * p) * (DD * PP) + i;
        float s2 = 0.0f;
        #pragma unroll
        for (int d = 0; d < DD; ++d) {
            float v = pp[d * PP];
            s2 = fmaf(v, v, s2);
            float m2 = -2.0f * v;
            pt[p][i][d] = pack2(m2, m2);
        }
        p2s[p][i] = s2;
    }

    // ---- x chunk for this warp's column block (packed), shared by both ----
    const float* xb = x + b * (DD * LL);
    const int j0 = w * WBLK;
    u64 xp[DD][CP2];
    u64 px2[CP2];
    {
        u64 z = pack2(0.0f, 0.0f);
        #pragma unroll
        for (int k2 = 0; k2 < CP2; ++k2) px2[k2] = z;
    }
    #pragma unroll
    for (int d = 0; d < DD; ++d) {
        const float* px = xb + d * LL + j0 + CPL * lane;
        float4 v0 = *reinterpret_cast<const float4*>(px);
        float4 v1 = *reinterpret_cast<const float4*>(px + 4);
        xp[d][0] = pack2(v0.x, v0.y);
        xp[d][1] = pack2(v0.z, v0.w);
        xp[d][2] = pack2(v1.x, v1.y);
        xp[d][3] = pack2(v1.z, v1.w);
        #pragma unroll
        for (int k2 = 0; k2 < CP2; ++k2)
            px2[k2] = ffma2(xp[d][k2], xp[d][k2], px2[k2]);
    }
    __syncthreads();   // pattern table ready

    float Dp[2][CPL];  // previous DP row per problem

    #pragma unroll 1
    for (int t = 0; t < PP + NBLK - 1; ++t) {
        const int i = t - w;
        if (i >= 0 && i < PP) {
            // ---- cost rows for both problems (interleaved packed FMAs) ----
            u64 cc[2][CP2];
            #pragma unroll
            for (int p = 0; p < 2; ++p) {
                float p2b = p2s[p][i];
                u64 p2b2 = pack2(p2b, p2b);
                #pragma unroll
                for (int k2 = 0; k2 < CP2; ++k2) cc[p][k2] = fadd2(p2b2, px2[k2]);
            }
            #pragma unroll
            for (int d = 0; d < DD; ++d) {
                u64 pb0 = pt[0][i][d];
                u64 pb1 = pt[1][i][d];
                #pragma unroll
                for (int k2 = 0; k2 < CP2; ++k2) {
                    cc[0][k2] = ffma2(pb0, xp[d][k2], cc[0][k2]);
                    cc[1][k2] = ffma2(pb1, xp[d][k2], cc[1][k2]);
                }
            }
            float c[2][CPL];
            #pragma unroll
            for (int p = 0; p < 2; ++p)
                #pragma unroll
                for (int k2 = 0; k2 < CP2; ++k2)
                    unpack2(cc[p][k2], c[p][2 * k2], c[p][2 * k2 + 1]);

            // ---- boundary carries (barrier-ordered smem) ----
            float bl[2], bm[2];
            #pragma unroll
            for (int p = 0; p < 2; ++p) {
                if (w == 0) {
                    bl[p] = (i == 0) ? 0.0f : BIGV;  // D[0,0] seed enters as v
                    bm[p] = BIGV;
                } else {
                    bl[p] = carry[p][w - 1][i];
                    bm[p] = (i > 0) ? carry[p][w - 1][i - 1] : BIGV;
                }
            }

            // ---- local inclusive composites per problem ----
            float A[2][CPL], Bv[2][CPL];
            float shin0 = __shfl_up_sync(FULL, Dp[0][CPL - 1], 1);
            float shin1 = __shfl_up_sync(FULL, Dp[1][CPL - 1], 1);
            float shin[2] = {shin0, shin1};
            #pragma unroll
            for (int p = 0; p < 2; ++p) {
                if (i == 0) {
                    A[p][0] = c[p][0]; Bv[p][0] = BIGV;
                    #pragma unroll
                    for (int k = 1; k < CPL; ++k) {
                        A[p][k] = A[p][k - 1] + c[p][k];
                        Bv[p][k] = BIGV;
                    }
                } else {
                    float m0 = fminf((lane == 0) ? bm[p] : shin[p], Dp[p][0]);
                    A[p][0]  = c[p][0];
                    Bv[p][0] = c[p][0] + m0;
                    #pragma unroll
                    for (int k = 1; k < CPL; ++k) {
                        float mk = fminf(Dp[p][k - 1], Dp[p][k]);
                        A[p][k]  = A[p][k - 1] + c[p][k];
                        Bv[p][k] = fminf(c[p][k] + mk, Bv[p][k - 1] + c[p][k]);
                    }
                }
            }

            // ---- composite warp scans, both problems interleaved ----
            float Aw0 = A[0][CPL - 1], Bw0 = Bv[0][CPL - 1];
            float Aw1 = A[1][CPL - 1], Bw1 = Bv[1][CPL - 1];
            #pragma unroll
            for (int o = 1; o < 32; o <<= 1) {
                float Au0 = __shfl_up_sync(FULL, Aw0, o);
                float Bu0 = __shfl_up_sync(FULL, Bw0, o);
                float Au1 = __shfl_up_sync(FULL, Aw1, o);
                float Bu1 = __shfl_up_sync(FULL, Bw1, o);
                if (lane >= o) {
                    Bw0 = fminf(Bw0, Bu0 + Aw0);  Aw0 = Aw0 + Au0;
                    Bw1 = fminf(Bw1, Bu1 + Aw1);  Aw1 = Aw1 + Au1;
                }
            }
            float Ae0 = __shfl_up_sync(FULL, Aw0, 1);
            float Be0 = __shfl_up_sync(FULL, Bw0, 1);
            float Ae1 = __shfl_up_sync(FULL, Aw1, 1);
            float Be1 = __shfl_up_sync(FULL, Bw1, 1);
            float vin[2];
            vin[0] = (lane == 0) ? bl[0] : fminf(Be0, bl[0] + Ae0);
            vin[1] = (lane == 0) ? bl[1] : fminf(Be1, bl[1] + Ae1);

            // ---- outputs: cur = min(B, vin + A) ----
            float cur[2][CPL];
            #pragma unroll
            for (int p = 0; p < 2; ++p)
                #pragma unroll
                for (int k = 0; k < CPL; ++k)
                    cur[p][k] = fminf(Bv[p][k], vin[p] + A[p][k]);

            // ---- publish carries for the warp to the right ----
            if (w < NBLK - 1 && lane == 31) {
                carry[0][w][i] = cur[0][CPL - 1];
                carry[1][w][i] = cur[1][CPL - 1];
            }

            // ---- output: cols 992..1023 = lanes 28..31 of last warp ----
            if (w == NBLK - 1 && lane >= 28) {
                const int off = i * LOUT + (lane - 28) * CPL;
                float* po0 = out + ((b * NP + np) * PP) * LOUT + off;
                float* po1 = out + ((b * NP + np + 16) * PP) * LOUT + off;
                *reinterpret_cast<float4*>(po0)     = make_float4(cur[0][0], cur[0][1], cur[0][2], cur[0][3]);
                *reinterpret_cast<float4*>(po0 + 4) = make_float4(cur[0][4], cur[0][5], cur[0][6], cur[0][7]);
                *reinterpret_cast<float4*>(po1)     = make_float4(cur[1][0], cur[1][1], cur[1][2], cur[1][3]);
                *reinterpret_cast<float4*>(po1 + 4) = make_float4(cur[1][4], cur[1][5], cur[1][6], cur[1][7]);
            }

            #pragma unroll
            for (int p = 0; p < 2; ++p)
                #pragma unroll
                for (int k = 0; k < CPL; ++k) Dp[p][k] = cur[p][k];
        }
        __syncthreads();
    }
}

extern "C" void kernel_launch(void* const* d_in, const int* in_sizes, int n_in,
                              void* d_out, int out_size) {
    const float* x     = (const float*)d_in[0];   // [32, 12, 1024]
    const float* patts = (const float*)d_in[1];   // [32, 12, 32]
    float* out = (float*)d_out;                   // [32, 32, 32, 32]
    (void)in_sizes; (void)n_in; (void)out_size;
    dtw_fused_kernel<<<NB * (NP / 2), 128>>>(x, patts, out);
}